// round 11
// baseline (speedup 1.0000x reference)
#include <cuda_runtime.h>
#include <cuda_fp16.h>
#include <cstdint>

// ---------------------------------------------------------------------------
// FanoCoupling: persistent-CTA HMMA pipeline, 512 threads, direct stores.
//
//   W = [W1|W2]; A0=W1x0 A1=W1x1 A3=W1x3 A4=W1x4 B1=W2x1 B2=W2x2 B3=W2x3 B5=W2x5
//   out0=x0 out1=x1 out3=x3
//   out2 = x2 + g0*(A0+B1+b)
//   out4 = x4 + g1*(A0+B3+b)
//   out5 = x5 + g3*(A1+B3+b) + g6*(A4+B2+b)
//   out6 = x6 + g2*(A0+B5+b) + g4*(A4+B1+b) + g5*(A3+B2+b)
//
// Per 32-row tile: cp.async double-buffered fp32 load; pass-through colonies
// copied out immediately; fp32->fp16 convert; mma.sync m16n8k16 (fp32 accum);
// epilogue reads fp32 residual from smem and stores straight to GMEM.
// Warp (of 16) = 16 rows x 8 z.
// ---------------------------------------------------------------------------

#define ROW 448
#define TROWS 32
#define BSTR 452                        // floats per buffered row (16B pad)
#define BUF_FLOATS (TROWS * BSTR)       // 14464
#define STR 72                          // halves per fp16 row
#define XH_COLONY (TROWS * STR)         // 2304
#define WH_HALF (64 * STR)              // 4608
#define SMEM_BYTES (2 * BUF_FLOATS * 4 + (6 * XH_COLONY + 2 * WH_HALF) * 2) // 161792
#define NTHR 512

__device__ __half whg[8192];            // [h][z][f] fp16 weights

__global__ void pack_w(const float* __restrict__ W) {
    int i = blockIdx.x * 256 + threadIdx.x;
    if (i < 8192) {
        int z = i >> 7, f = i & 127;
        whg[(f >> 6) * 4096 + z * 64 + (f & 63)] = __float2half_rn(W[i]);
    }
}

__device__ __forceinline__ uint32_t s2u(const void* p) {
    uint32_t a;
    asm("{ .reg .u64 t; cvta.to.shared.u64 t, %1; cvt.u32.u64 %0, t; }" : "=r"(a) : "l"(p));
    return a;
}
__device__ __forceinline__ void cpasync16(uint32_t dst, const void* src) {
    asm volatile("cp.async.cg.shared.global [%0], [%1], 16;" :: "r"(dst), "l"(src));
}
#define CP_COMMIT() asm volatile("cp.async.commit_group;" ::: "memory")
#define CP_WAIT(N)  asm volatile("cp.async.wait_group %0;" :: "n"(N) : "memory")

__device__ __forceinline__ void ldm4(uint32_t* r, uint32_t addr) {
    asm volatile("ldmatrix.sync.aligned.m8n8.x4.shared.b16 {%0,%1,%2,%3}, [%4];"
                 : "=r"(r[0]), "=r"(r[1]), "=r"(r[2]), "=r"(r[3]) : "r"(addr));
}
__device__ __forceinline__ void ldm2(uint32_t* r, uint32_t addr) {
    asm volatile("ldmatrix.sync.aligned.m8n8.x2.shared.b16 {%0,%1}, [%2];"
                 : "=r"(r[0]), "=r"(r[1]) : "r"(addr));
}
__device__ __forceinline__ void mma16816(float* d, const uint32_t* a, const uint32_t* b) {
    asm volatile("mma.sync.aligned.m16n8k16.row.col.f32.f16.f16.f32 "
                 "{%0,%1,%2,%3}, {%4,%5,%6,%7}, {%8,%9}, {%0,%1,%2,%3};"
                 : "+f"(d[0]), "+f"(d[1]), "+f"(d[2]), "+f"(d[3])
                 : "r"(a[0]), "r"(a[1]), "r"(a[2]), "r"(a[3]), "r"(b[0]), "r"(b[1]));
}

__global__ __launch_bounds__(NTHR, 1)
void fano_mma(const float* __restrict__ x, const float* __restrict__ bias,
              const float* __restrict__ gates, float* __restrict__ out, int nrows)
{
    extern __shared__ float smf[];
    float*  bufs[2] = { smf, smf + BUF_FLOATS };
    __half* xh = reinterpret_cast<__half*>(smf + 2 * BUF_FLOATS);
    __half* wh = xh + 6 * XH_COLONY;

    const int tid = threadIdx.x;
    const int G = gridDim.x;
    const int NT = (nrows + TROWS - 1) / TROWS;

    // --- stage fp16 W once --------------------------------------------------
    {
        const uint4* wg = reinterpret_cast<const uint4*>(whg);
        for (int i = tid; i < 1024; i += NTHR) {
            int hz = i >> 3, f8 = (i & 7) * 8;
            *reinterpret_cast<uint4*>(wh + hz * STR + f8) = wg[i];
        }
    }

    const int warp = tid >> 5, lane = tid & 31;
    const int rbase = (warp & 1) * 16;          // m tile
    const int zbase = ((warp >> 1) & 7) * 8;    // 8-z tile
    const int qrow = lane >> 2, qcol = (lane & 3) * 2;

    // --- gates softmax + hoisted bias ---------------------------------------
    float g[7];
    {
        float graw[7];
        #pragma unroll
        for (int i = 0; i < 7; i++) graw[i] = gates[i];
        float m = graw[0];
        #pragma unroll
        for (int i = 1; i < 7; i++) m = fmaxf(m, graw[i]);
        float s = 0.f;
        #pragma unroll
        for (int i = 0; i < 7; i++) { g[i] = expf(graw[i] - m); s += g[i]; }
        float inv = 1.f / s;
        #pragma unroll
        for (int i = 0; i < 7; i++) g[i] *= inv;
    }
    const float bz0 = bias[zbase + qcol], bz1 = bias[zbase + qcol + 1];

    // fragment base addresses
    const int agrp = lane >> 3, alr = lane & 7;
    const int arow = rbase + alr + ((agrp & 1) ? 8 : 0);
    const int akk  = (agrp & 2) ? 8 : 0;
    const uint32_t aoff = s2u(xh) + (uint32_t)(arow * STR + akk) * 2;
    const int blr = lane & 7, bgrp = (lane >> 3) & 1;
    const uint32_t boff = s2u(wh) + (uint32_t)((zbase + blr) * STR + bgrp * 8) * 2;

    const uint32_t bufu[2] = { s2u(bufs[0]), s2u(bufs[1]) };

    // --- prologue: prefetch first tile --------------------------------------
    int t = blockIdx.x;
    if (t < NT) {
        const float* src = x + (long long)t * TROWS * ROW;
        long long rowb = (long long)t * TROWS;
        for (int i = tid; i < TROWS * 112; i += NTHR) {
            int r = i / 112, ch = i % 112;
            if (rowb + r < nrows)
                cpasync16(bufu[0] + (uint32_t)(r * BSTR + ch * 4) * 4,
                          src + r * ROW + ch * 4);
        }
    }
    CP_COMMIT();

    int pb = 0;
    for (; t < NT; t += G, pb ^= 1) {
        // prefetch next tile into other buffer
        int tn = t + G;
        if (tn < NT) {
            const float* src = x + (long long)tn * TROWS * ROW;
            long long rowb = (long long)tn * TROWS;
            for (int i = tid; i < TROWS * 112; i += NTHR) {
                int r = i / 112, ch = i % 112;
                if (rowb + r < nrows)
                    cpasync16(bufu[pb ^ 1] + (uint32_t)(r * BSTR + ch * 4) * 4,
                              src + r * ROW + ch * 4);
            }
            CP_COMMIT();
            CP_WAIT(1);
        } else {
            CP_COMMIT();
            CP_WAIT(0);
        }
        __syncthreads();

        float* buf = bufs[pb];
        const long long rowb = (long long)t * TROWS;

        // --- pass-through colonies 0,1,3 out immediately --------------------
        for (int i = tid; i < TROWS * 48; i += NTHR) {
            int r = i / 48, rem = i % 48, ci = rem / 16, f4 = (rem & 15) * 4;
            int c = (ci < 2) ? ci : 3;
            long long row = rowb + r;
            if (row < nrows)
                *reinterpret_cast<float4*>(out + row * (long long)ROW + c * 64 + f4) =
                    *reinterpret_cast<const float4*>(buf + r * BSTR + c * 64 + f4);
        }

        // --- convert colonies 0..5 fp32 -> fp16 -----------------------------
        for (int i = tid; i < TROWS * 96; i += NTHR) {
            int r = i / 96, rem = i % 96, c = rem >> 4, f4 = (rem & 15) * 4;
            float4 v = *reinterpret_cast<const float4*>(buf + r * BSTR + c * 64 + f4);
            __half2* p = reinterpret_cast<__half2*>(xh + c * XH_COLONY + r * STR + f4);
            p[0] = __floats2half2_rn(v.x, v.y);
            p[1] = __floats2half2_rn(v.z, v.w);
        }
        __syncthreads();

        // --- MMA: acc[res][frag] --------------------------------------------
        float acc[8][4];
        #pragma unroll
        for (int j = 0; j < 8; j++)
            #pragma unroll
            for (int q = 0; q < 4; q++) acc[j][q] = 0.f;

        #pragma unroll
        for (int ks = 0; ks < 4; ks++) {
            const uint32_t k0b = (uint32_t)(ks * 16) * 2;
            uint32_t a[6][4];
            #pragma unroll
            for (int c = 0; c < 6; c++)
                ldm4(a[c], aoff + (uint32_t)(c * XH_COLONY) * 2 + k0b);
            uint32_t b1[2], b2[2];
            ldm2(b1, boff + k0b);
            ldm2(b2, boff + (uint32_t)(WH_HALF) * 2 + k0b);
            mma16816(acc[0], a[0], b1);   // A0
            mma16816(acc[1], a[1], b1);   // A1
            mma16816(acc[2], a[3], b1);   // A3
            mma16816(acc[3], a[4], b1);   // A4
            mma16816(acc[4], a[1], b2);   // B1
            mma16816(acc[5], a[2], b2);   // B2
            mma16816(acc[6], a[3], b2);   // B3
            mma16816(acc[7], a[5], b2);   // B5
        }

        // --- epilogue: fp32 residual from buf, direct STG -------------------
        const int z0 = zbase + qcol;
        #pragma unroll
        for (int hh = 0; hh < 2; hh++) {
            const int rl = rbase + qrow + hh * 8;
            const long long row = rowb + rl;
            if (row >= nrows) continue;
            const float* bp = buf + rl * BSTR;
            float* orow = out + row * (long long)ROW;
            const int i0 = hh * 2, i1 = hh * 2 + 1;
            float2 o;
            o.x = bp[2*64 + z0]     + g[0] * (acc[0][i0] + acc[4][i0] + bz0);
            o.y = bp[2*64 + z0 + 1] + g[0] * (acc[0][i1] + acc[4][i1] + bz1);
            *reinterpret_cast<float2*>(orow + 2*64 + z0) = o;
            o.x = bp[4*64 + z0]     + g[1] * (acc[0][i0] + acc[6][i0] + bz0);
            o.y = bp[4*64 + z0 + 1] + g[1] * (acc[0][i1] + acc[6][i1] + bz1);
            *reinterpret_cast<float2*>(orow + 4*64 + z0) = o;
            o.x = bp[5*64 + z0]     + g[3] * (acc[1][i0] + acc[6][i0] + bz0)
                                    + g[6] * (acc[3][i0] + acc[5][i0] + bz0);
            o.y = bp[5*64 + z0 + 1] + g[3] * (acc[1][i1] + acc[6][i1] + bz1)
                                    + g[6] * (acc[3][i1] + acc[5][i1] + bz1);
            *reinterpret_cast<float2*>(orow + 5*64 + z0) = o;
            o.x = bp[6*64 + z0]     + g[2] * (acc[0][i0] + acc[7][i0] + bz0)
                                    + g[4] * (acc[3][i0] + acc[4][i0] + bz0)
                                    + g[5] * (acc[2][i0] + acc[5][i0] + bz0);
            o.y = bp[6*64 + z0 + 1] + g[2] * (acc[0][i1] + acc[7][i1] + bz1)
                                    + g[4] * (acc[3][i1] + acc[4][i1] + bz1)
                                    + g[5] * (acc[2][i1] + acc[5][i1] + bz1);
            *reinterpret_cast<float2*>(orow + 6*64 + z0) = o;
        }
        __syncthreads();   // all reads of buf/xh done before next prefetch/convert
    }
}

extern "C" void kernel_launch(void* const* d_in, const int* in_sizes, int n_in,
                              void* d_out, int out_size) {
    const float* x     = (const float*)d_in[0];   // colony_states [B,7,64]
    const float* W     = (const float*)d_in[1];   // [64,128]
    const float* bias  = (const float*)d_in[2];   // [64]
    const float* gates = (const float*)d_in[3];   // [7]
    float* out = (float*)d_out;

    int nrows = in_sizes[0] / ROW;
    pack_w<<<32, 256>>>(W);
    cudaFuncSetAttribute(fano_mma,
                         cudaFuncAttributeMaxDynamicSharedMemorySize, SMEM_BYTES);
    fano_mma<<<148, NTHR, SMEM_BYTES>>>(x, bias, gates, out, nrows);
}

// round 12
// speedup vs baseline: 1.3446x; 1.3446x over previous
#include <cuda_runtime.h>
#include <cuda_fp16.h>
#include <cstdint>

// ---------------------------------------------------------------------------
// FanoCoupling: persistent HMMA pipeline, 2 independent CTAs/SM.
//
//   W = [W1|W2]; A0=W1x0 A1=W1x1 A3=W1x3 A4=W1x4 B1=W2x1 B2=W2x2 B3=W2x3 B5=W2x5
//   out0=x0 out1=x1 out3=x3
//   out2 = x2 + g0*(A0+B1+b)
//   out4 = x4 + g1*(A0+B3+b)
//   out5 = x5 + g3*(A1+B3+b) + g6*(A4+B2+b)
//   out6 = x6 + g2*(A0+B5+b) + g4*(A4+B1+b) + g5*(A3+B2+b)
//
// Per 16-row tile: cp.async double-buffered fp32 load; convert fp32->fp16
// fused with pass-through stores of colonies 0/1/3; mma.sync m16n8k16
// (fp32 accum); epilogue reads fp32 residual from smem, stores direct.
// 256 thr/CTA; warp = 16 rows x 8 z.  2 barriers per tile.
// ---------------------------------------------------------------------------

#define ROW 448
#define TROWS 16
#define BSTR 452                        // floats per buffered row (16B pad)
#define BUF_FLOATS (TROWS * BSTR)       // 7232
#define STR 72                          // halves per fp16 row
#define XH_COLONY (TROWS * STR)         // 1152
#define WH_HALF (64 * STR)              // 4608
#define SMEM_BYTES (2 * BUF_FLOATS * 4 + (6 * XH_COLONY + 2 * WH_HALF) * 2) // 90112
#define NTHR 256

__device__ __half whg[8192];            // [h][z][f] fp16 weights

__global__ void pack_w(const float* __restrict__ W) {
    int i = blockIdx.x * 256 + threadIdx.x;
    if (i < 8192) {
        int z = i >> 7, f = i & 127;
        whg[(f >> 6) * 4096 + z * 64 + (f & 63)] = __float2half_rn(W[i]);
    }
}

__device__ __forceinline__ uint32_t s2u(const void* p) {
    uint32_t a;
    asm("{ .reg .u64 t; cvta.to.shared.u64 t, %1; cvt.u32.u64 %0, t; }" : "=r"(a) : "l"(p));
    return a;
}
__device__ __forceinline__ void cpasync16(uint32_t dst, const void* src) {
    asm volatile("cp.async.cg.shared.global [%0], [%1], 16;" :: "r"(dst), "l"(src));
}
#define CP_COMMIT() asm volatile("cp.async.commit_group;" ::: "memory")
#define CP_WAIT(N)  asm volatile("cp.async.wait_group %0;" :: "n"(N) : "memory")

__device__ __forceinline__ void ldm4(uint32_t* r, uint32_t addr) {
    asm volatile("ldmatrix.sync.aligned.m8n8.x4.shared.b16 {%0,%1,%2,%3}, [%4];"
                 : "=r"(r[0]), "=r"(r[1]), "=r"(r[2]), "=r"(r[3]) : "r"(addr));
}
__device__ __forceinline__ void ldm2(uint32_t* r, uint32_t addr) {
    asm volatile("ldmatrix.sync.aligned.m8n8.x2.shared.b16 {%0,%1}, [%2];"
                 : "=r"(r[0]), "=r"(r[1]) : "r"(addr));
}
__device__ __forceinline__ void mma16816(float* d, const uint32_t* a, const uint32_t* b) {
    asm volatile("mma.sync.aligned.m16n8k16.row.col.f32.f16.f16.f32 "
                 "{%0,%1,%2,%3}, {%4,%5,%6,%7}, {%8,%9}, {%0,%1,%2,%3};"
                 : "+f"(d[0]), "+f"(d[1]), "+f"(d[2]), "+f"(d[3])
                 : "r"(a[0]), "r"(a[1]), "r"(a[2]), "r"(a[3]), "r"(b[0]), "r"(b[1]));
}

__global__ __launch_bounds__(NTHR, 2)
void fano_mma(const float* __restrict__ x, const float* __restrict__ bias,
              const float* __restrict__ gates, float* __restrict__ out, int nrows)
{
    extern __shared__ float smf[];
    float*  bufs[2] = { smf, smf + BUF_FLOATS };
    __half* xh = reinterpret_cast<__half*>(smf + 2 * BUF_FLOATS);
    __half* wh = xh + 6 * XH_COLONY;

    const int tid = threadIdx.x;
    const int G = gridDim.x;
    const int NT = (nrows + TROWS - 1) / TROWS;

    // --- stage fp16 W once --------------------------------------------------
    {
        const uint4* wg = reinterpret_cast<const uint4*>(whg);
        for (int i = tid; i < 1024; i += NTHR) {
            int hz = i >> 3, f8 = (i & 7) * 8;
            *reinterpret_cast<uint4*>(wh + hz * STR + f8) = wg[i];
        }
    }

    const int warp = tid >> 5, lane = tid & 31;
    const int zbase = warp * 8;                 // warp's 8-z tile (8 warps x 8 = 64)
    const int qrow = lane >> 2, qcol = (lane & 3) * 2;

    // --- gates softmax + hoisted bias ---------------------------------------
    float g[7];
    {
        float graw[7];
        #pragma unroll
        for (int i = 0; i < 7; i++) graw[i] = gates[i];
        float m = graw[0];
        #pragma unroll
        for (int i = 1; i < 7; i++) m = fmaxf(m, graw[i]);
        float s = 0.f;
        #pragma unroll
        for (int i = 0; i < 7; i++) { g[i] = expf(graw[i] - m); s += g[i]; }
        float inv = 1.f / s;
        #pragma unroll
        for (int i = 0; i < 7; i++) g[i] *= inv;
    }
    const float bz0 = bias[zbase + qcol], bz1 = bias[zbase + qcol + 1];

    // fragment base addresses (fixed per thread)
    const int agrp = lane >> 3, alr = lane & 7;
    const int arow = alr + ((agrp & 1) ? 8 : 0);
    const int akk  = (agrp & 2) ? 8 : 0;
    const uint32_t aoff = s2u(xh) + (uint32_t)(arow * STR + akk) * 2;
    const int blr = lane & 7, bgrp = (lane >> 3) & 1;
    const uint32_t boff = s2u(wh) + (uint32_t)((zbase + blr) * STR + bgrp * 8) * 2;

    const uint32_t bufu[2] = { s2u(bufs[0]), s2u(bufs[1]) };

    // --- prologue: prefetch first tile --------------------------------------
    int t = blockIdx.x;
    if (t < NT) {
        const float* src = x + (long long)t * TROWS * ROW;
        long long rowb = (long long)t * TROWS;
        for (int i = tid; i < TROWS * 112; i += NTHR) {
            int r = i / 112, ch = i % 112;
            if (rowb + r < nrows)
                cpasync16(bufu[0] + (uint32_t)(r * BSTR + ch * 4) * 4,
                          src + r * ROW + ch * 4);
        }
    }
    CP_COMMIT();

    int pb = 0;
    for (; t < NT; t += G, pb ^= 1) {
        CP_WAIT(0);
        __syncthreads();      // tile t visible to all; buf[pb^1] readers done

        // prefetch next tile into other buffer (overlaps all processing below)
        int tn = t + G;
        if (tn < NT) {
            const float* src = x + (long long)tn * TROWS * ROW;
            long long rowb = (long long)tn * TROWS;
            for (int i = tid; i < TROWS * 112; i += NTHR) {
                int r = i / 112, ch = i % 112;
                if (rowb + r < nrows)
                    cpasync16(bufu[pb ^ 1] + (uint32_t)(r * BSTR + ch * 4) * 4,
                              src + r * ROW + ch * 4);
            }
        }
        CP_COMMIT();

        float* buf = bufs[pb];
        const long long rowb = (long long)t * TROWS;

        // --- convert colonies 0..5 fp32->fp16, fused pass-through 0/1/3 ----
        for (int i = tid; i < TROWS * 96; i += NTHR) {
            int r = i / 96, rem = i % 96, c = rem >> 4, f4 = (rem & 15) * 4;
            float4 v = *reinterpret_cast<const float4*>(buf + r * BSTR + c * 64 + f4);
            __half2* p = reinterpret_cast<__half2*>(xh + c * XH_COLONY + r * STR + f4);
            p[0] = __floats2half2_rn(v.x, v.y);
            p[1] = __floats2half2_rn(v.z, v.w);
            if (c == 0 || c == 1 || c == 3) {        // pass-through colonies
                long long row = rowb + r;
                if (row < nrows)
                    *reinterpret_cast<float4*>(out + row * (long long)ROW + c * 64 + f4) =
                        v;
            }
        }
        __syncthreads();      // xh ready for ldmatrix

        // --- MMA: acc[res][frag] --------------------------------------------
        float acc[8][4];
        #pragma unroll
        for (int j = 0; j < 8; j++)
            #pragma unroll
            for (int q = 0; q < 4; q++) acc[j][q] = 0.f;

        #pragma unroll
        for (int ks = 0; ks < 4; ks++) {
            const uint32_t k0b = (uint32_t)(ks * 16) * 2;
            uint32_t a[6][4];
            #pragma unroll
            for (int c = 0; c < 6; c++)
                ldm4(a[c], aoff + (uint32_t)(c * XH_COLONY) * 2 + k0b);
            uint32_t b1[2], b2[2];
            ldm2(b1, boff + k0b);
            ldm2(b2, boff + (uint32_t)(WH_HALF) * 2 + k0b);
            mma16816(acc[0], a[0], b1);   // A0
            mma16816(acc[1], a[1], b1);   // A1
            mma16816(acc[2], a[3], b1);   // A3
            mma16816(acc[3], a[4], b1);   // A4
            mma16816(acc[4], a[1], b2);   // B1
            mma16816(acc[5], a[2], b2);   // B2
            mma16816(acc[6], a[3], b2);   // B3
            mma16816(acc[7], a[5], b2);   // B5
        }

        // --- epilogue: fp32 residual from buf, direct STG -------------------
        const int z0 = zbase + qcol;
        #pragma unroll
        for (int hh = 0; hh < 2; hh++) {
            const int rl = qrow + hh * 8;
            const long long row = rowb + rl;
            if (row >= nrows) continue;
            const float* bp = buf + rl * BSTR;
            float* orow = out + row * (long long)ROW;
            const int i0 = hh * 2, i1 = hh * 2 + 1;
            float2 o;
            o.x = bp[2*64 + z0]     + g[0] * (acc[0][i0] + acc[4][i0] + bz0);
            o.y = bp[2*64 + z0 + 1] + g[0] * (acc[0][i1] + acc[4][i1] + bz1);
            *reinterpret_cast<float2*>(orow + 2*64 + z0) = o;
            o.x = bp[4*64 + z0]     + g[1] * (acc[0][i0] + acc[6][i0] + bz0);
            o.y = bp[4*64 + z0 + 1] + g[1] * (acc[0][i1] + acc[6][i1] + bz1);
            *reinterpret_cast<float2*>(orow + 4*64 + z0) = o;
            o.x = bp[5*64 + z0]     + g[3] * (acc[1][i0] + acc[6][i0] + bz0)
                                    + g[6] * (acc[3][i0] + acc[5][i0] + bz0);
            o.y = bp[5*64 + z0 + 1] + g[3] * (acc[1][i1] + acc[6][i1] + bz1)
                                    + g[6] * (acc[3][i1] + acc[5][i1] + bz1);
            *reinterpret_cast<float2*>(orow + 5*64 + z0) = o;
            o.x = bp[6*64 + z0]     + g[2] * (acc[0][i0] + acc[7][i0] + bz0)
                                    + g[4] * (acc[3][i0] + acc[4][i0] + bz0)
                                    + g[5] * (acc[2][i0] + acc[5][i0] + bz0);
            o.y = bp[6*64 + z0 + 1] + g[2] * (acc[0][i1] + acc[7][i1] + bz1)
                                    + g[4] * (acc[3][i1] + acc[4][i1] + bz1)
                                    + g[5] * (acc[2][i1] + acc[5][i1] + bz1);
            *reinterpret_cast<float2*>(orow + 6*64 + z0) = o;
        }
        // no end barrier: next iteration's top sync orders buf reuse
    }
}

extern "C" void kernel_launch(void* const* d_in, const int* in_sizes, int n_in,
                              void* d_out, int out_size) {
    const float* x     = (const float*)d_in[0];   // colony_states [B,7,64]
    const float* W     = (const float*)d_in[1];   // [64,128]
    const float* bias  = (const float*)d_in[2];   // [64]
    const float* gates = (const float*)d_in[3];   // [7]
    float* out = (float*)d_out;

    int nrows = in_sizes[0] / ROW;
    pack_w<<<32, 256>>>(W);
    cudaFuncSetAttribute(fano_mma,
                         cudaFuncAttributeMaxDynamicSharedMemorySize, SMEM_BYTES);
    fano_mma<<<296, NTHR, SMEM_BYTES>>>(x, bias, gates, out, nrows);
}

// round 13
// speedup vs baseline: 1.4399x; 1.0709x over previous
#include <cuda_runtime.h>
#include <cuda_fp16.h>
#include <cstdint>

// ---------------------------------------------------------------------------
// FanoCoupling: persistent HMMA pipeline, 2 CTAs/SM, warp-specialized.
//
//   W = [W1|W2]; A0=W1x0 A1=W1x1 A3=W1x3 A4=W1x4 B1=W2x1 B2=W2x2 B3=W2x3 B5=W2x5
//   out0=x0 out1=x1 out3=x3
//   out2 = x2 + g0*(A0+B1+b)
//   out4 = x4 + g1*(A0+B3+b)
//   out5 = x5 + g3*(A1+B3+b) + g6*(A4+B2+b)
//   out6 = x6 + g2*(A0+B5+b) + g4*(A4+B1+b) + g5*(A3+B2+b)
//
// Per 16-row tile: cp.async double-buffered fp32 load; all warps convert
// fp32->fp16; then warps 0-3 do MMA (warp = 16 rows x 16 z, nt=2) + epilogue
// while warps 4-7 stream the pass-through colonies 0/1/3 out.  A-fragment
// ldmatrix redundancy halved vs R11 (4 warps instead of 8 read the A tiles).
// ---------------------------------------------------------------------------

#define ROW 448
#define TROWS 16
#define BSTR 452                        // floats per buffered row (16B pad)
#define BUF_FLOATS (TROWS * BSTR)       // 7232
#define STR 72                          // halves per fp16 row
#define XH_COLONY (TROWS * STR)         // 1152
#define WH_HALF (64 * STR)              // 4608
#define SMEM_BYTES (2 * BUF_FLOATS * 4 + (6 * XH_COLONY + 2 * WH_HALF) * 2) // 90112
#define NTHR 256

__device__ __half whg[8192];            // [h][z][f] fp16 weights

__global__ void pack_w(const float* __restrict__ W) {
    int i = blockIdx.x * 256 + threadIdx.x;
    if (i < 8192) {
        int z = i >> 7, f = i & 127;
        whg[(f >> 6) * 4096 + z * 64 + (f & 63)] = __float2half_rn(W[i]);
    }
}

__device__ __forceinline__ uint32_t s2u(const void* p) {
    uint32_t a;
    asm("{ .reg .u64 t; cvta.to.shared.u64 t, %1; cvt.u32.u64 %0, t; }" : "=r"(a) : "l"(p));
    return a;
}
__device__ __forceinline__ void cpasync16(uint32_t dst, const void* src) {
    asm volatile("cp.async.cg.shared.global [%0], [%1], 16;" :: "r"(dst), "l"(src));
}
#define CP_COMMIT() asm volatile("cp.async.commit_group;" ::: "memory")
#define CP_WAIT(N)  asm volatile("cp.async.wait_group %0;" :: "n"(N) : "memory")

__device__ __forceinline__ void ldm4(uint32_t* r, uint32_t addr) {
    asm volatile("ldmatrix.sync.aligned.m8n8.x4.shared.b16 {%0,%1,%2,%3}, [%4];"
                 : "=r"(r[0]), "=r"(r[1]), "=r"(r[2]), "=r"(r[3]) : "r"(addr));
}
__device__ __forceinline__ void mma16816(float* d, const uint32_t* a, const uint32_t* b) {
    asm volatile("mma.sync.aligned.m16n8k16.row.col.f32.f16.f16.f32 "
                 "{%0,%1,%2,%3}, {%4,%5,%6,%7}, {%8,%9}, {%0,%1,%2,%3};"
                 : "+f"(d[0]), "+f"(d[1]), "+f"(d[2]), "+f"(d[3])
                 : "r"(a[0]), "r"(a[1]), "r"(a[2]), "r"(a[3]), "r"(b[0]), "r"(b[1]));
}

__global__ __launch_bounds__(NTHR, 2)
void fano_mma(const float* __restrict__ x, const float* __restrict__ bias,
              const float* __restrict__ gates, float* __restrict__ out, int nrows)
{
    extern __shared__ float smf[];
    float*  bufs[2] = { smf, smf + BUF_FLOATS };
    __half* xh = reinterpret_cast<__half*>(smf + 2 * BUF_FLOATS);
    __half* wh = xh + 6 * XH_COLONY;

    const int tid = threadIdx.x;
    const int G = gridDim.x;
    const int NT = (nrows + TROWS - 1) / TROWS;

    // --- stage fp16 W once --------------------------------------------------
    {
        const uint4* wg = reinterpret_cast<const uint4*>(whg);
        for (int i = tid; i < 1024; i += NTHR) {
            int hz = i >> 3, f8 = (i & 7) * 8;
            *reinterpret_cast<uint4*>(wh + hz * STR + f8) = wg[i];
        }
    }

    const int warp = tid >> 5, lane = tid & 31;
    const bool mma_warp = (warp < 4);
    const int zbase = (warp & 3) * 16;          // 16-z tile (4 warps cover 64 z)
    const int qrow = lane >> 2, qcol = (lane & 3) * 2;

    // --- gates softmax + hoisted bias ---------------------------------------
    float g[7];
    {
        float graw[7];
        #pragma unroll
        for (int i = 0; i < 7; i++) graw[i] = gates[i];
        float m = graw[0];
        #pragma unroll
        for (int i = 1; i < 7; i++) m = fmaxf(m, graw[i]);
        float s = 0.f;
        #pragma unroll
        for (int i = 0; i < 7; i++) { g[i] = expf(graw[i] - m); s += g[i]; }
        float inv = 1.f / s;
        #pragma unroll
        for (int i = 0; i < 7; i++) g[i] *= inv;
    }
    float bz[2][2];
    #pragma unroll
    for (int nt = 0; nt < 2; nt++) {
        bz[nt][0] = bias[zbase + nt * 8 + qcol];
        bz[nt][1] = bias[zbase + nt * 8 + qcol + 1];
    }

    // fragment base addresses (fixed per thread)
    const int agrp = lane >> 3, alr = lane & 7;
    const int arow = alr + ((agrp & 1) ? 8 : 0);
    const int akk  = (agrp & 2) ? 8 : 0;
    const uint32_t aoff = s2u(xh) + (uint32_t)(arow * STR + akk) * 2;
    // B via ldm4: groups -> [z0-8,k0][z0-8,k8][z8-16,k0][z8-16,k8]
    const int bz8  = (agrp & 2) ? 8 : 0;        // nt sub-tile
    const int bkk  = (agrp & 1) ? 8 : 0;
    const uint32_t boff = s2u(wh) + (uint32_t)((zbase + bz8 + alr) * STR + bkk) * 2;

    const uint32_t bufu[2] = { s2u(bufs[0]), s2u(bufs[1]) };

    // --- prologue: prefetch first tile --------------------------------------
    int t = blockIdx.x;
    if (t < NT) {
        const float* src = x + (long long)t * TROWS * ROW;
        long long rowb = (long long)t * TROWS;
        for (int i = tid; i < TROWS * 112; i += NTHR) {
            int r = i / 112, ch = i % 112;
            if (rowb + r < nrows)
                cpasync16(bufu[0] + (uint32_t)(r * BSTR + ch * 4) * 4,
                          src + r * ROW + ch * 4);
        }
    }
    CP_COMMIT();

    int pb = 0;
    for (; t < NT; t += G, pb ^= 1) {
        CP_WAIT(0);
        __syncthreads();      // tile t visible; buf[pb^1] readers done

        // prefetch next tile into other buffer (overlaps everything below)
        int tn = t + G;
        if (tn < NT) {
            const float* src = x + (long long)tn * TROWS * ROW;
            long long rowb = (long long)tn * TROWS;
            for (int i = tid; i < TROWS * 112; i += NTHR) {
                int r = i / 112, ch = i % 112;
                if (rowb + r < nrows)
                    cpasync16(bufu[pb ^ 1] + (uint32_t)(r * BSTR + ch * 4) * 4,
                              src + r * ROW + ch * 4);
            }
        }
        CP_COMMIT();

        float* buf = bufs[pb];
        const long long rowb = (long long)t * TROWS;

        // --- all warps: convert colonies 0..5 fp32 -> fp16 ------------------
        for (int i = tid; i < TROWS * 96; i += NTHR) {
            int r = i / 96, rem = i % 96, c = rem >> 4, f4 = (rem & 15) * 4;
            float4 v = *reinterpret_cast<const float4*>(buf + r * BSTR + c * 64 + f4);
            __half2 h01 = __floats2half2_rn(v.x, v.y);
            __half2 h23 = __floats2half2_rn(v.z, v.w);
            *reinterpret_cast<uint2*>(xh + c * XH_COLONY + r * STR + f4) =
                make_uint2(*reinterpret_cast<uint32_t*>(&h01),
                           *reinterpret_cast<uint32_t*>(&h23));
        }
        __syncthreads();      // xh ready

        if (mma_warp) {
            // --- MMA: acc[res][nt][frag], warp = 16 rows x 16 z -------------
            float acc[8][2][4];
            #pragma unroll
            for (int j = 0; j < 8; j++)
                #pragma unroll
                for (int nt = 0; nt < 2; nt++)
                    #pragma unroll
                    for (int q = 0; q < 4; q++) acc[j][nt][q] = 0.f;

            #pragma unroll
            for (int ks = 0; ks < 4; ks++) {
                const uint32_t k0b = (uint32_t)(ks * 16) * 2;
                uint32_t a[6][4];
                #pragma unroll
                for (int c = 0; c < 6; c++)
                    ldm4(a[c], aoff + (uint32_t)(c * XH_COLONY) * 2 + k0b);
                uint32_t b1[4], b2[4];   // [0,1]=nt0 {k0,k8}, [2,3]=nt1
                ldm4(b1, boff + k0b);
                ldm4(b2, boff + (uint32_t)(WH_HALF) * 2 + k0b);
                #pragma unroll
                for (int nt = 0; nt < 2; nt++) {
                    mma16816(acc[0][nt], a[0], b1 + nt * 2);   // A0
                    mma16816(acc[1][nt], a[1], b1 + nt * 2);   // A1
                    mma16816(acc[2][nt], a[3], b1 + nt * 2);   // A3
                    mma16816(acc[3][nt], a[4], b1 + nt * 2);   // A4
                    mma16816(acc[4][nt], a[1], b2 + nt * 2);   // B1
                    mma16816(acc[5][nt], a[2], b2 + nt * 2);   // B2
                    mma16816(acc[6][nt], a[3], b2 + nt * 2);   // B3
                    mma16816(acc[7][nt], a[5], b2 + nt * 2);   // B5
                }
            }

            // --- epilogue: fp32 residual from buf, direct STG ---------------
            #pragma unroll
            for (int nt = 0; nt < 2; nt++) {
                const int z0 = zbase + nt * 8 + qcol;
                const float b0 = bz[nt][0], b1v = bz[nt][1];
                #pragma unroll
                for (int hh = 0; hh < 2; hh++) {
                    const int rl = qrow + hh * 8;
                    const long long row = rowb + rl;
                    if (row >= nrows) continue;
                    const float* bp = buf + rl * BSTR;
                    float* orow = out + row * (long long)ROW;
                    const int i0 = hh * 2, i1 = hh * 2 + 1;
                    float2 o;
                    o.x = bp[2*64 + z0]     + g[0] * (acc[0][nt][i0] + acc[4][nt][i0] + b0);
                    o.y = bp[2*64 + z0 + 1] + g[0] * (acc[0][nt][i1] + acc[4][nt][i1] + b1v);
                    *reinterpret_cast<float2*>(orow + 2*64 + z0) = o;
                    o.x = bp[4*64 + z0]     + g[1] * (acc[0][nt][i0] + acc[6][nt][i0] + b0);
                    o.y = bp[4*64 + z0 + 1] + g[1] * (acc[0][nt][i1] + acc[6][nt][i1] + b1v);
                    *reinterpret_cast<float2*>(orow + 4*64 + z0) = o;
                    o.x = bp[5*64 + z0]     + g[3] * (acc[1][nt][i0] + acc[6][nt][i0] + b0)
                                            + g[6] * (acc[3][nt][i0] + acc[5][nt][i0] + b0);
                    o.y = bp[5*64 + z0 + 1] + g[3] * (acc[1][nt][i1] + acc[6][nt][i1] + b1v)
                                            + g[6] * (acc[3][nt][i1] + acc[5][nt][i1] + b1v);
                    *reinterpret_cast<float2*>(orow + 5*64 + z0) = o;
                    o.x = bp[6*64 + z0]     + g[2] * (acc[0][nt][i0] + acc[7][nt][i0] + b0)
                                            + g[4] * (acc[3][nt][i0] + acc[4][nt][i0] + b0)
                                            + g[5] * (acc[2][nt][i0] + acc[5][nt][i0] + b0);
                    o.y = bp[6*64 + z0 + 1] + g[2] * (acc[0][nt][i1] + acc[7][nt][i1] + b1v)
                                            + g[4] * (acc[3][nt][i1] + acc[4][nt][i1] + b1v)
                                            + g[5] * (acc[2][nt][i1] + acc[5][nt][i1] + b1v);
                    *reinterpret_cast<float2*>(orow + 6*64 + z0) = o;
                }
            }
        } else {
            // --- warps 4-7: pass-through colonies 0,1,3 (overlaps MMA) ------
            for (int i = tid - 128; i < TROWS * 48; i += 128) {
                int r = i / 48, rem = i % 48, ci = rem / 16, f4 = (rem & 15) * 4;
                int c = (ci < 2) ? ci : 3;
                long long row = rowb + r;
                if (row < nrows)
                    *reinterpret_cast<float4*>(out + row * (long long)ROW + c * 64 + f4) =
                        *reinterpret_cast<const float4*>(buf + r * BSTR + c * 64 + f4);
            }
        }
        // no tail barrier: next iteration's top sync orders buf reuse
    }
}

extern "C" void kernel_launch(void* const* d_in, const int* in_sizes, int n_in,
                              void* d_out, int out_size) {
    const float* x     = (const float*)d_in[0];   // colony_states [B,7,64]
    const float* W     = (const float*)d_in[1];   // [64,128]
    const float* bias  = (const float*)d_in[2];   // [64]
    const float* gates = (const float*)d_in[3];   // [7]
    float* out = (float*)d_out;

    int nrows = in_sizes[0] / ROW;
    pack_w<<<32, 256>>>(W);
    cudaFuncSetAttribute(fano_mma,
                         cudaFuncAttributeMaxDynamicSharedMemorySize, SMEM_BYTES);
    fano_mma<<<296, NTHR, SMEM_BYTES>>>(x, bias, gates, out, nrows);
}